// round 2
// baseline (speedup 1.0000x reference)
#include <cuda_runtime.h>
#include <math.h>

// ---------------- problem constants ----------------
#define HH 56
#define WW_ 56
#define CC 512
#define NHEAD 16
#define WSZ 7
#define SSH 3
#define HID 2048
#define HD 32
#define NTOK 49           // tokens per window
#define NWH 8
#define NWW 8
#define NWIN 64
#define BB 16
#define TOT (BB*HH*WW_)   // 50176 tokens
#define LN_EPS 1e-5f
#define ATT_SCALE 0.17677669529663687f  // 32^-0.5

// ---------------- scratch (device globals, no allocs) ----------------
__device__ float g_h   [TOT * CC];        // LN1+windowed  (reused as h2)
__device__ float g_qkv [TOT * 3 * CC];    // qkv
__device__ float g_o   [TOT * CC];        // attention out (window layout)
__device__ float g_proj[TOT * CC];        // proj out (window layout)
__device__ float g_act [TOT * HID];       // fc1 activations

// ---------------- LayerNorm (optionally fused shift+window gather) ----------------
template<bool GATHER>
__global__ void ln_kernel(const float* __restrict__ src,
                          const float* __restrict__ scale,
                          const float* __restrict__ bias,
                          float* __restrict__ dst)
{
    int t = blockIdx.x;
    const float* sp;
    if (GATHER) {
        int b   = t / (NWIN * NTOK);
        int rem = t % (NWIN * NTOK);
        int win = rem / NTOK, pos = rem % NTOK;
        int wh = win / NWW, ww = win % NWW;
        int p = pos / WSZ, q = pos % WSZ;
        int row = (wh * WSZ + p + SSH) % HH;     // roll(-3)
        int col = (ww * WSZ + q + SSH) % WW_;
        sp = src + ((size_t)(b * HH + row) * WW_ + col) * CC;
    } else {
        sp = src + (size_t)t * CC;
    }
    float* dp = dst + (size_t)t * CC;

    int tid = threadIdx.x;                 // 128 threads, 4 floats each
    float4 v = *(const float4*)(sp + tid * 4);
    float s  = v.x + v.y + v.z + v.w;
    float s2 = v.x*v.x + v.y*v.y + v.z*v.z + v.w*v.w;

    __shared__ float red[8];
    #pragma unroll
    for (int off = 16; off > 0; off >>= 1) {
        s  += __shfl_down_sync(0xffffffffu, s,  off);
        s2 += __shfl_down_sync(0xffffffffu, s2, off);
    }
    int wid = tid >> 5, lane = tid & 31;
    if (lane == 0) { red[wid] = s; red[4 + wid] = s2; }
    __syncthreads();
    if (tid == 0) {
        float S  = red[0] + red[1] + red[2] + red[3];
        float S2 = red[4] + red[5] + red[6] + red[7];
        float mu  = S * (1.0f / CC);
        float var = S2 * (1.0f / CC) - mu * mu;
        red[0] = mu;
        red[1] = rsqrtf(var + LN_EPS);
    }
    __syncthreads();
    float mu = red[0], rs = red[1];
    float4 sc = *(const float4*)(scale + tid * 4);
    float4 bi = *(const float4*)(bias  + tid * 4);
    float4 o;
    o.x = (v.x - mu) * rs * sc.x + bi.x;
    o.y = (v.y - mu) * rs * sc.y + bi.y;
    o.z = (v.z - mu) * rs * sc.z + bi.z;
    o.w = (v.w - mu) * rs * sc.w + bi.w;
    *(float4*)(dp + tid * 4) = o;
}

// ---------------- SGEMM: C = A[M,K] @ B[K,N] + bias, epilogue variants ----------------
// EPI: 0 = bias only, 1 = bias + exact GELU, 2 = bias + residual add
__device__ __forceinline__ float gelu_exact(float x) {
    return 0.5f * x * (1.0f + erff(x * 0.70710678118654752f));
}

template<int EPI>
__global__ __launch_bounds__(256, 2)
void sgemm_kernel(const float* __restrict__ A, const float* __restrict__ B,
                  const float* __restrict__ bias, float* __restrict__ Cout,
                  const float* __restrict__ res, int M, int N, int K)
{
    __shared__ float As[8][128];
    __shared__ float Bs[8][128];

    int bx = blockIdx.x;           // N tile
    int by = blockIdx.y;           // M tile
    int tid = threadIdx.x;         // 256
    int tx = tid & 15, ty = tid >> 4;

    float acc[8][8];
    #pragma unroll
    for (int i = 0; i < 8; i++)
        #pragma unroll
        for (int j = 0; j < 8; j++) acc[i][j] = 0.0f;

    int arow = tid >> 1;           // 0..127
    int acol = (tid & 1) * 4;      // 0 or 4
    int brow = tid >> 5;           // 0..7
    int bcol = (tid & 31) * 4;     // 0..124

    const float* Aptr = A + (size_t)(by * 128 + arow) * K + acol;
    const float* Bptr = B + (size_t)brow * N + bx * 128 + bcol;

    for (int k0 = 0; k0 < K; k0 += 8) {
        float4 a4 = *(const float4*)(Aptr + k0);
        float4 b4 = *(const float4*)(Bptr + (size_t)k0 * N);
        As[acol + 0][arow] = a4.x;
        As[acol + 1][arow] = a4.y;
        As[acol + 2][arow] = a4.z;
        As[acol + 3][arow] = a4.w;
        *(float4*)&Bs[brow][bcol] = b4;
        __syncthreads();
        #pragma unroll
        for (int kk = 0; kk < 8; kk++) {
            float4 a0 = *(const float4*)&As[kk][ty * 8];
            float4 a1 = *(const float4*)&As[kk][ty * 8 + 4];
            float4 b0 = *(const float4*)&Bs[kk][tx * 8];
            float4 b1 = *(const float4*)&Bs[kk][tx * 8 + 4];
            float ra[8] = {a0.x, a0.y, a0.z, a0.w, a1.x, a1.y, a1.z, a1.w};
            float rb[8] = {b0.x, b0.y, b0.z, b0.w, b1.x, b1.y, b1.z, b1.w};
            #pragma unroll
            for (int i = 0; i < 8; i++)
                #pragma unroll
                for (int j = 0; j < 8; j++)
                    acc[i][j] += ra[i] * rb[j];
        }
        __syncthreads();
    }

    int row0 = by * 128 + ty * 8;
    int col0 = bx * 128 + tx * 8;
    float4 bia0 = *(const float4*)(bias + col0);
    float4 bia1 = *(const float4*)(bias + col0 + 4);
    float bb[8] = {bia0.x, bia0.y, bia0.z, bia0.w, bia1.x, bia1.y, bia1.z, bia1.w};

    #pragma unroll
    for (int i = 0; i < 8; i++) {
        size_t off = (size_t)(row0 + i) * N + col0;
        #pragma unroll
        for (int j0 = 0; j0 < 8; j0 += 4) {
            float4 v;
            v.x = acc[i][j0 + 0] + bb[j0 + 0];
            v.y = acc[i][j0 + 1] + bb[j0 + 1];
            v.z = acc[i][j0 + 2] + bb[j0 + 2];
            v.w = acc[i][j0 + 3] + bb[j0 + 3];
            if (EPI == 1) {
                v.x = gelu_exact(v.x); v.y = gelu_exact(v.y);
                v.z = gelu_exact(v.z); v.w = gelu_exact(v.w);
            }
            if (EPI == 2) {
                float4 r4 = *(const float4*)(res + off + j0);
                v.x += r4.x; v.y += r4.y; v.z += r4.z; v.w += r4.w;
            }
            *(float4*)(Cout + off + j0) = v;
        }
    }
}

// ---------------- windowed attention: one block per (window, head) ----------------
__global__ void attn_kernel(const float* __restrict__ qkv,
                            const float* __restrict__ rpb_table,
                            float* __restrict__ o)
{
    int head = blockIdx.x;
    int win  = blockIdx.y;             // b*NWIN + w
    int wloc = win % NWIN;
    int wh = wloc / NWW, ww = wloc % NWW;

    __shared__ float Qs[NTOK][33];
    __shared__ float Ks[NTOK][33];
    __shared__ float Vs[NTOK][33];
    __shared__ float Ss[NTOK][NTOK];
    __shared__ float rpbs[169];
    __shared__ int   regn[NTOK];

    int tid = threadIdx.x;             // 128

    const float* base = qkv + (size_t)win * NTOK * (3 * CC) + head * HD;
    for (int i = tid; i < NTOK * 8; i += 128) {
        int n = i >> 3, d4 = (i & 7) * 4;
        const float* rp = base + (size_t)n * (3 * CC);
        float4 q4 = *(const float4*)(rp + d4);
        float4 k4 = *(const float4*)(rp + CC + d4);
        float4 v4 = *(const float4*)(rp + 2 * CC + d4);
        Qs[n][d4] = q4.x; Qs[n][d4+1] = q4.y; Qs[n][d4+2] = q4.z; Qs[n][d4+3] = q4.w;
        Ks[n][d4] = k4.x; Ks[n][d4+1] = k4.y; Ks[n][d4+2] = k4.z; Ks[n][d4+3] = k4.w;
        Vs[n][d4] = v4.x; Vs[n][d4+1] = v4.y; Vs[n][d4+2] = v4.z; Vs[n][d4+3] = v4.w;
    }
    for (int i = tid; i < 169; i += 128) rpbs[i] = rpb_table[i * NHEAD + head];
    if (tid < NTOK) {
        int p = tid / WSZ, q = tid % WSZ;
        int r = wh * WSZ + p, c = ww * WSZ + q;       // shifted-frame coords
        int rr = (r < 49) ? 0 : ((r < 53) ? 1 : 2);
        int rc = (c < 49) ? 0 : ((c < 53) ? 1 : 2);
        regn[tid] = rr * 3 + rc;
    }
    __syncthreads();

    // scores + rpb + mask
    for (int i = tid; i < NTOK * NTOK; i += 128) {
        int n = i / NTOK, m = i % NTOK;
        float acc = 0.0f;
        #pragma unroll
        for (int d = 0; d < HD; d++) acc += Qs[n][d] * Ks[m][d];
        int in_ = n / WSZ, jn = n % WSZ;
        int im  = m / WSZ, jm = m % WSZ;
        int ridx = (jn - jm + 6) * 13 + (in_ - im + 6);
        float val = acc * ATT_SCALE + rpbs[ridx];
        if (regn[n] != regn[m]) val -= 100.0f;
        Ss[n][m] = val;
    }
    __syncthreads();

    // row softmax (thread r owns row r)
    if (tid < NTOK) {
        float mx = -1e30f;
        #pragma unroll 7
        for (int m = 0; m < NTOK; m++) mx = fmaxf(mx, Ss[tid][m]);
        float sum = 0.0f;
        #pragma unroll 7
        for (int m = 0; m < NTOK; m++) {
            float e = expf(Ss[tid][m] - mx);
            Ss[tid][m] = e;
            sum += e;
        }
        float inv = 1.0f / sum;
        #pragma unroll 7
        for (int m = 0; m < NTOK; m++) Ss[tid][m] *= inv;
    }
    __syncthreads();

    // O = P @ V
    float* obase = o + (size_t)win * NTOK * CC + head * HD;
    for (int i = tid; i < NTOK * HD; i += 128) {
        int n = i >> 5, d = i & 31;
        float acc = 0.0f;
        #pragma unroll 7
        for (int m = 0; m < NTOK; m++) acc += Ss[n][m] * Vs[m][d];
        obase[(size_t)n * CC + d] = acc;
    }
}

// ---------------- window reverse + unshift + residual ----------------
__global__ void scatter_add_kernel(const float* __restrict__ x,
                                   const float* __restrict__ p,
                                   float* __restrict__ y)
{
    int t = blockIdx.x;
    int b = t / (HH * WW_);
    int rem = t % (HH * WW_);
    int r = rem / WW_, c = rem % WW_;
    int R  = (r - SSH + HH) % HH;       // reverse roll(+3)
    int Cc = (c - SSH + WW_) % WW_;
    int win = (R / WSZ) * NWW + (Cc / WSZ);
    int pos = (R % WSZ) * WSZ + (Cc % WSZ);
    const float* sp = p + ((size_t)(b * NWIN + win) * NTOK + pos) * CC;
    const float* xp = x + (size_t)t * CC;
    float* yp = y + (size_t)t * CC;
    int tid = threadIdx.x;
    float4 a  = *(const float4*)(xp + tid * 4);
    float4 pr = *(const float4*)(sp + tid * 4);
    float4 o;
    o.x = a.x + pr.x; o.y = a.y + pr.y; o.z = a.z + pr.z; o.w = a.w + pr.w;
    *(float4*)(yp + tid * 4) = o;
}

// ---------------- host launcher ----------------
extern "C" void kernel_launch(void* const* d_in, const int* in_sizes, int n_in,
                              void* d_out, int out_size)
{
    const float* x      = (const float*)d_in[0];
    const float* ln1_s  = (const float*)d_in[1];
    const float* ln1_b  = (const float*)d_in[2];
    const float* qkv_w  = (const float*)d_in[3];
    const float* qkv_b  = (const float*)d_in[4];
    const float* rpb    = (const float*)d_in[5];
    const float* proj_w = (const float*)d_in[6];
    const float* proj_b = (const float*)d_in[7];
    const float* ln2_s  = (const float*)d_in[8];
    const float* ln2_b  = (const float*)d_in[9];
    const float* fc1_w  = (const float*)d_in[10];
    const float* fc1_b  = (const float*)d_in[11];
    const float* fc2_w  = (const float*)d_in[12];
    const float* fc2_b  = (const float*)d_in[13];
    float* out = (float*)d_out;

    float *ph, *pqkv, *po, *pproj, *pact;
    cudaGetSymbolAddress((void**)&ph,    g_h);
    cudaGetSymbolAddress((void**)&pqkv,  g_qkv);
    cudaGetSymbolAddress((void**)&po,    g_o);
    cudaGetSymbolAddress((void**)&pproj, g_proj);
    cudaGetSymbolAddress((void**)&pact,  g_act);

    // 1. LN1 + shift + window partition
    ln_kernel<true><<<TOT, 128>>>(x, ln1_s, ln1_b, ph);
    // 2. QKV GEMM [50176,512]x[512,1536]
    sgemm_kernel<0><<<dim3(1536/128, TOT/128), 256>>>(ph, qkv_w, qkv_b, pqkv, nullptr, TOT, 1536, 512);
    // 3. windowed attention
    attn_kernel<<<dim3(NHEAD, BB * NWIN), 128>>>(pqkv, rpb, po);
    // 4. proj GEMM [50176,512]x[512,512]
    sgemm_kernel<0><<<dim3(512/128, TOT/128), 256>>>(po, proj_w, proj_b, pproj, nullptr, TOT, 512, 512);
    // 5. window reverse + unshift + residual
    scatter_add_kernel<<<TOT, 128>>>(x, pproj, out);
    // 6. LN2
    ln_kernel<false><<<TOT, 128>>>(out, ln2_s, ln2_b, ph);
    // 7. FC1 + GELU [50176,512]x[512,2048]
    sgemm_kernel<1><<<dim3(HID/128, TOT/128), 256>>>(ph, fc1_w, fc1_b, pact, nullptr, TOT, HID, 512);
    // 8. FC2 + residual [50176,2048]x[2048,512]
    sgemm_kernel<2><<<dim3(512/128, TOT/128), 256>>>(pact, fc2_w, fc2_b, out, out, TOT, 512, HID);
}

// round 3
// speedup vs baseline: 2.4927x; 2.4927x over previous
#include <cuda_runtime.h>
#include <math.h>
#include <stdint.h>

// ---------------- problem constants ----------------
#define HH 56
#define WW_ 56
#define CC 512
#define NHEAD 16
#define WSZ 7
#define SSH 3
#define HID 2048
#define HD 32
#define NTOK 49           // tokens per window
#define NWH 8
#define NWW 8
#define NWIN 64
#define BB 16
#define TOT (BB*HH*WW_)   // 50176 tokens
#define LN_EPS 1e-5f
#define ATT_SCALE 0.17677669529663687f  // 32^-0.5

// ---------------- scratch (device globals, no allocs) ----------------
__device__ float g_h   [TOT * CC];        // LN1+windowed  (reused as h2)
__device__ float g_qkv [TOT * 3 * CC];    // qkv
__device__ float g_o   [TOT * CC];        // attention out (window layout)
__device__ float g_proj[TOT * CC];        // proj out (window layout)
__device__ float g_act [TOT * HID];       // fc1 activations

// ---------------- LayerNorm (optionally fused shift+window gather) ----------------
template<bool GATHER>
__global__ void ln_kernel(const float* __restrict__ src,
                          const float* __restrict__ scale,
                          const float* __restrict__ bias,
                          float* __restrict__ dst)
{
    int t = blockIdx.x;
    const float* sp;
    if (GATHER) {
        int b   = t / (NWIN * NTOK);
        int rem = t % (NWIN * NTOK);
        int win = rem / NTOK, pos = rem % NTOK;
        int wh = win / NWW, ww = win % NWW;
        int p = pos / WSZ, q = pos % WSZ;
        int row = (wh * WSZ + p + SSH) % HH;     // roll(-3)
        int col = (ww * WSZ + q + SSH) % WW_;
        sp = src + ((size_t)(b * HH + row) * WW_ + col) * CC;
    } else {
        sp = src + (size_t)t * CC;
    }
    float* dp = dst + (size_t)t * CC;

    int tid = threadIdx.x;                 // 128 threads, 4 floats each
    float4 v = *(const float4*)(sp + tid * 4);
    float s  = v.x + v.y + v.z + v.w;
    float s2 = v.x*v.x + v.y*v.y + v.z*v.z + v.w*v.w;

    __shared__ float red[8];
    #pragma unroll
    for (int off = 16; off > 0; off >>= 1) {
        s  += __shfl_down_sync(0xffffffffu, s,  off);
        s2 += __shfl_down_sync(0xffffffffu, s2, off);
    }
    int wid = tid >> 5, lane = tid & 31;
    if (lane == 0) { red[wid] = s; red[4 + wid] = s2; }
    __syncthreads();
    if (tid == 0) {
        float S  = red[0] + red[1] + red[2] + red[3];
        float S2 = red[4] + red[5] + red[6] + red[7];
        float mu  = S * (1.0f / CC);
        float var = S2 * (1.0f / CC) - mu * mu;
        red[0] = mu;
        red[1] = rsqrtf(var + LN_EPS);
    }
    __syncthreads();
    float mu = red[0], rs = red[1];
    float4 sc = *(const float4*)(scale + tid * 4);
    float4 bi = *(const float4*)(bias  + tid * 4);
    float4 o;
    o.x = (v.x - mu) * rs * sc.x + bi.x;
    o.y = (v.y - mu) * rs * sc.y + bi.y;
    o.z = (v.z - mu) * rs * sc.z + bi.z;
    o.w = (v.w - mu) * rs * sc.w + bi.w;
    *(float4*)(dp + tid * 4) = o;
}

// ---------------- TF32 tensor-core GEMM ----------------
// C[M,N] = A[M,K] @ B[K,N] + bias, epilogues: 0=bias, 1=bias+GELU, 2=bias+residual
__device__ __forceinline__ float gelu_exact(float x) {
    return 0.5f * x * (1.0f + erff(x * 0.70710678118654752f));
}

__device__ __forceinline__ uint32_t f2tf32(float x) {
    uint32_t r;
    asm("cvt.rna.tf32.f32 %0, %1;" : "=r"(r) : "f"(x));
    return r;
}

#define SST 136   // smem row stride (floats): (lane&3)*8 + lane>>2 covers 32 banks

template<int EPI>
__global__ __launch_bounds__(256, 2)
void tgemm_kernel(const float* __restrict__ A, const float* __restrict__ B,
                  const float* __restrict__ bias, float* __restrict__ Cout,
                  const float* __restrict__ res, int M, int N, int K)
{
    extern __shared__ uint32_t sh[];
    uint32_t* As = sh;                      // [2][16][SST]
    uint32_t* Bs = sh + 2 * 16 * SST;       // [2][16][SST]

    const int bx = blockIdx.x;              // N tile
    const int by = blockIdx.y;              // M tile
    const int tid = threadIdx.x;
    const int wid = tid >> 5, lane = tid & 31;
    const int wm = wid & 1;                 // warp m: 0..1  (64 rows each)
    const int wn = wid >> 1;                // warp n: 0..3  (32 cols each)
    const int lr = lane >> 2;               // 0..7
    const int lc = lane & 3;                // 0..3

    float acc[4][4][4];
    #pragma unroll
    for (int i = 0; i < 4; i++)
        #pragma unroll
        for (int j = 0; j < 4; j++)
            #pragma unroll
            for (int r = 0; r < 4; r++) acc[i][j][r] = 0.0f;

    // staging assignments
    const int a_row = tid >> 1;                    // 0..127
    const int a_kb  = (tid & 1) * 8;               // 0 or 8
    const float* Ag = A + (size_t)(by * 128 + a_row) * K + a_kb;
    const int b_row0 = tid >> 5;                   // p = tid: row=tid/32
    const int b_col0 = (tid & 31) * 4;
    // second B element: p = tid + 256 -> row = 8 + tid/32, same col
    const float* Bg = B + (size_t)b_row0 * N + bx * 128 + b_col0;

    const int NS = K >> 4;

    float4 ra0, ra1, rb0, rb1;

    // prologue: stage 0
    ra0 = *(const float4*)(Ag);
    ra1 = *(const float4*)(Ag + 4);
    rb0 = *(const float4*)(Bg);
    rb1 = *(const float4*)(Bg + (size_t)8 * N);
    {
        uint32_t* Ad = As;  // buf 0
        Ad[(a_kb+0)*SST + a_row] = f2tf32(ra0.x);
        Ad[(a_kb+1)*SST + a_row] = f2tf32(ra0.y);
        Ad[(a_kb+2)*SST + a_row] = f2tf32(ra0.z);
        Ad[(a_kb+3)*SST + a_row] = f2tf32(ra0.w);
        Ad[(a_kb+4)*SST + a_row] = f2tf32(ra1.x);
        Ad[(a_kb+5)*SST + a_row] = f2tf32(ra1.y);
        Ad[(a_kb+6)*SST + a_row] = f2tf32(ra1.z);
        Ad[(a_kb+7)*SST + a_row] = f2tf32(ra1.w);
        uint32_t* Bd = Bs;
        uint4 t0 = make_uint4(f2tf32(rb0.x), f2tf32(rb0.y), f2tf32(rb0.z), f2tf32(rb0.w));
        uint4 t1 = make_uint4(f2tf32(rb1.x), f2tf32(rb1.y), f2tf32(rb1.z), f2tf32(rb1.w));
        *(uint4*)&Bd[b_row0*SST + b_col0]     = t0;
        *(uint4*)&Bd[(b_row0+8)*SST + b_col0] = t1;
    }
    __syncthreads();

    for (int s = 0; s < NS; s++) {
        // prefetch next stage
        if (s + 1 < NS) {
            int k0 = (s + 1) * 16;
            ra0 = *(const float4*)(Ag + k0);
            ra1 = *(const float4*)(Ag + k0 + 4);
            rb0 = *(const float4*)(Bg + (size_t)k0 * N);
            rb1 = *(const float4*)(Bg + (size_t)(k0 + 8) * N);
        }

        const uint32_t* Ab = As + (s & 1) * 16 * SST;
        const uint32_t* Bb = Bs + (s & 1) * 16 * SST;

        #pragma unroll
        for (int kk = 0; kk < 16; kk += 8) {
            uint32_t af[4][4], bf[4][2];
            #pragma unroll
            for (int mi = 0; mi < 4; mi++) {
                int m = wm * 64 + mi * 16 + lr;
                af[mi][0] = Ab[(kk + lc    )*SST + m];
                af[mi][1] = Ab[(kk + lc    )*SST + m + 8];
                af[mi][2] = Ab[(kk + lc + 4)*SST + m];
                af[mi][3] = Ab[(kk + lc + 4)*SST + m + 8];
            }
            #pragma unroll
            for (int ni = 0; ni < 4; ni++) {
                int n = wn * 32 + ni * 8 + lr;
                bf[ni][0] = Bb[(kk + lc    )*SST + n];
                bf[ni][1] = Bb[(kk + lc + 4)*SST + n];
            }
            #pragma unroll
            for (int mi = 0; mi < 4; mi++)
                #pragma unroll
                for (int ni = 0; ni < 4; ni++) {
                    asm volatile(
                        "mma.sync.aligned.m16n8k8.row.col.f32.tf32.tf32.f32 "
                        "{%0,%1,%2,%3}, {%4,%5,%6,%7}, {%8,%9}, {%0,%1,%2,%3};"
                        : "+f"(acc[mi][ni][0]), "+f"(acc[mi][ni][1]),
                          "+f"(acc[mi][ni][2]), "+f"(acc[mi][ni][3])
                        : "r"(af[mi][0]), "r"(af[mi][1]), "r"(af[mi][2]), "r"(af[mi][3]),
                          "r"(bf[ni][0]), "r"(bf[ni][1]));
                }
        }

        // store prefetched stage into other buffer
        if (s + 1 < NS) {
            uint32_t* Ad = As + ((s + 1) & 1) * 16 * SST;
            uint32_t* Bd = Bs + ((s + 1) & 1) * 16 * SST;
            Ad[(a_kb+0)*SST + a_row] = f2tf32(ra0.x);
            Ad[(a_kb+1)*SST + a_row] = f2tf32(ra0.y);
            Ad[(a_kb+2)*SST + a_row] = f2tf32(ra0.z);
            Ad[(a_kb+3)*SST + a_row] = f2tf32(ra0.w);
            Ad[(a_kb+4)*SST + a_row] = f2tf32(ra1.x);
            Ad[(a_kb+5)*SST + a_row] = f2tf32(ra1.y);
            Ad[(a_kb+6)*SST + a_row] = f2tf32(ra1.z);
            Ad[(a_kb+7)*SST + a_row] = f2tf32(ra1.w);
            uint4 t0 = make_uint4(f2tf32(rb0.x), f2tf32(rb0.y), f2tf32(rb0.z), f2tf32(rb0.w));
            uint4 t1 = make_uint4(f2tf32(rb1.x), f2tf32(rb1.y), f2tf32(rb1.z), f2tf32(rb1.w));
            *(uint4*)&Bd[b_row0*SST + b_col0]     = t0;
            *(uint4*)&Bd[(b_row0+8)*SST + b_col0] = t1;
        }
        __syncthreads();
    }

    // ---------------- epilogue ----------------
    const int m_base = by * 128 + wm * 64;
    const int n_base = bx * 128 + wn * 32;

    float2 bv[4];
    #pragma unroll
    for (int ni = 0; ni < 4; ni++) {
        int col = n_base + ni * 8 + 2 * lc;
        bv[ni] = *(const float2*)(bias + col);
    }

    #pragma unroll
    for (int mi = 0; mi < 4; mi++) {
        int r0 = m_base + mi * 16 + lr;
        int r1 = r0 + 8;
        #pragma unroll
        for (int ni = 0; ni < 4; ni++) {
            int col = n_base + ni * 8 + 2 * lc;
            size_t off0 = (size_t)r0 * N + col;
            size_t off1 = (size_t)r1 * N + col;
            float2 v0, v1;
            v0.x = acc[mi][ni][0] + bv[ni].x;
            v0.y = acc[mi][ni][1] + bv[ni].y;
            v1.x = acc[mi][ni][2] + bv[ni].x;
            v1.y = acc[mi][ni][3] + bv[ni].y;
            if (EPI == 1) {
                v0.x = gelu_exact(v0.x); v0.y = gelu_exact(v0.y);
                v1.x = gelu_exact(v1.x); v1.y = gelu_exact(v1.y);
            }
            if (EPI == 2) {
                float2 q0 = *(const float2*)(res + off0);
                float2 q1 = *(const float2*)(res + off1);
                v0.x += q0.x; v0.y += q0.y;
                v1.x += q1.x; v1.y += q1.y;
            }
            *(float2*)(Cout + off0) = v0;
            *(float2*)(Cout + off1) = v1;
        }
    }
}

#define TGEMM_SMEM (2 * 16 * SST * 4 * 2)   // 69632 bytes

// ---------------- windowed attention: one block per (window, head) ----------------
__global__ void attn_kernel(const float* __restrict__ qkv,
                            const float* __restrict__ rpb_table,
                            float* __restrict__ o)
{
    int head = blockIdx.x;
    int win  = blockIdx.y;             // b*NWIN + w
    int wloc = win % NWIN;
    int wh = wloc / NWW, ww = wloc % NWW;

    __shared__ float Qs[NTOK][33];
    __shared__ float Ks[NTOK][33];
    __shared__ float Vs[NTOK][33];
    __shared__ float Ss[NTOK][NTOK];
    __shared__ float rpbs[169];
    __shared__ int   regn[NTOK];

    int tid = threadIdx.x;             // 128

    const float* base = qkv + (size_t)win * NTOK * (3 * CC) + head * HD;
    for (int i = tid; i < NTOK * 8; i += 128) {
        int n = i >> 3, d4 = (i & 7) * 4;
        const float* rp = base + (size_t)n * (3 * CC);
        float4 q4 = *(const float4*)(rp + d4);
        float4 k4 = *(const float4*)(rp + CC + d4);
        float4 v4 = *(const float4*)(rp + 2 * CC + d4);
        Qs[n][d4] = q4.x; Qs[n][d4+1] = q4.y; Qs[n][d4+2] = q4.z; Qs[n][d4+3] = q4.w;
        Ks[n][d4] = k4.x; Ks[n][d4+1] = k4.y; Ks[n][d4+2] = k4.z; Ks[n][d4+3] = k4.w;
        Vs[n][d4] = v4.x; Vs[n][d4+1] = v4.y; Vs[n][d4+2] = v4.z; Vs[n][d4+3] = v4.w;
    }
    for (int i = tid; i < 169; i += 128) rpbs[i] = rpb_table[i * NHEAD + head];
    if (tid < NTOK) {
        int p = tid / WSZ, q = tid % WSZ;
        int r = wh * WSZ + p, c = ww * WSZ + q;       // shifted-frame coords
        int rr = (r < 49) ? 0 : ((r < 53) ? 1 : 2);
        int rc = (c < 49) ? 0 : ((c < 53) ? 1 : 2);
        regn[tid] = rr * 3 + rc;
    }
    __syncthreads();

    // scores + rpb + mask
    for (int i = tid; i < NTOK * NTOK; i += 128) {
        int n = i / NTOK, m = i % NTOK;
        float acc = 0.0f;
        #pragma unroll
        for (int d = 0; d < HD; d++) acc += Qs[n][d] * Ks[m][d];
        int in_ = n / WSZ, jn = n % WSZ;
        int im  = m / WSZ, jm = m % WSZ;
        int ridx = (jn - jm + 6) * 13 + (in_ - im + 6);
        float val = acc * ATT_SCALE + rpbs[ridx];
        if (regn[n] != regn[m]) val -= 100.0f;
        Ss[n][m] = val;
    }
    __syncthreads();

    // row softmax (thread r owns row r)
    if (tid < NTOK) {
        float mx = -1e30f;
        #pragma unroll 7
        for (int m = 0; m < NTOK; m++) mx = fmaxf(mx, Ss[tid][m]);
        float sum = 0.0f;
        #pragma unroll 7
        for (int m = 0; m < NTOK; m++) {
            float e = expf(Ss[tid][m] - mx);
            Ss[tid][m] = e;
            sum += e;
        }
        float inv = 1.0f / sum;
        #pragma unroll 7
        for (int m = 0; m < NTOK; m++) Ss[tid][m] *= inv;
    }
    __syncthreads();

    // O = P @ V
    float* obase = o + (size_t)win * NTOK * CC + head * HD;
    for (int i = tid; i < NTOK * HD; i += 128) {
        int n = i >> 5, d = i & 31;
        float acc = 0.0f;
        #pragma unroll 7
        for (int m = 0; m < NTOK; m++) acc += Ss[n][m] * Vs[m][d];
        obase[(size_t)n * CC + d] = acc;
    }
}

// ---------------- window reverse + unshift + residual ----------------
__global__ void scatter_add_kernel(const float* __restrict__ x,
                                   const float* __restrict__ p,
                                   float* __restrict__ y)
{
    int t = blockIdx.x;
    int b = t / (HH * WW_);
    int rem = t % (HH * WW_);
    int r = rem / WW_, c = rem % WW_;
    int R  = (r - SSH + HH) % HH;       // reverse roll(+3)
    int Cc = (c - SSH + WW_) % WW_;
    int win = (R / WSZ) * NWW + (Cc / WSZ);
    int pos = (R % WSZ) * WSZ + (Cc % WSZ);
    const float* sp = p + ((size_t)(b * NWIN + win) * NTOK + pos) * CC;
    const float* xp = x + (size_t)t * CC;
    float* yp = y + (size_t)t * CC;
    int tid = threadIdx.x;
    float4 a  = *(const float4*)(xp + tid * 4);
    float4 pr = *(const float4*)(sp + tid * 4);
    float4 o;
    o.x = a.x + pr.x; o.y = a.y + pr.y; o.z = a.z + pr.z; o.w = a.w + pr.w;
    *(float4*)(yp + tid * 4) = o;
}

// ---------------- host launcher ----------------
extern "C" void kernel_launch(void* const* d_in, const int* in_sizes, int n_in,
                              void* d_out, int out_size)
{
    const float* x      = (const float*)d_in[0];
    const float* ln1_s  = (const float*)d_in[1];
    const float* ln1_b  = (const float*)d_in[2];
    const float* qkv_w  = (const float*)d_in[3];
    const float* qkv_b  = (const float*)d_in[4];
    const float* rpb    = (const float*)d_in[5];
    const float* proj_w = (const float*)d_in[6];
    const float* proj_b = (const float*)d_in[7];
    const float* ln2_s  = (const float*)d_in[8];
    const float* ln2_b  = (const float*)d_in[9];
    const float* fc1_w  = (const float*)d_in[10];
    const float* fc1_b  = (const float*)d_in[11];
    const float* fc2_w  = (const float*)d_in[12];
    const float* fc2_b  = (const float*)d_in[13];
    float* out = (float*)d_out;

    float *ph, *pqkv, *po, *pproj, *pact;
    cudaGetSymbolAddress((void**)&ph,    g_h);
    cudaGetSymbolAddress((void**)&pqkv,  g_qkv);
    cudaGetSymbolAddress((void**)&po,    g_o);
    cudaGetSymbolAddress((void**)&pproj, g_proj);
    cudaGetSymbolAddress((void**)&pact,  g_act);

    static int smem_set = 0;
    if (!smem_set) {
        cudaFuncSetAttribute(tgemm_kernel<0>, cudaFuncAttributeMaxDynamicSharedMemorySize, TGEMM_SMEM);
        cudaFuncSetAttribute(tgemm_kernel<1>, cudaFuncAttributeMaxDynamicSharedMemorySize, TGEMM_SMEM);
        cudaFuncSetAttribute(tgemm_kernel<2>, cudaFuncAttributeMaxDynamicSharedMemorySize, TGEMM_SMEM);
        smem_set = 1;
    }

    // 1. LN1 + shift + window partition
    ln_kernel<true><<<TOT, 128>>>(x, ln1_s, ln1_b, ph);
    // 2. QKV GEMM [50176,512]x[512,1536]
    tgemm_kernel<0><<<dim3(1536/128, TOT/128), 256, TGEMM_SMEM>>>(ph, qkv_w, qkv_b, pqkv, nullptr, TOT, 1536, 512);
    // 3. windowed attention
    attn_kernel<<<dim3(NHEAD, BB * NWIN), 128>>>(pqkv, rpb, po);
    // 4. proj GEMM [50176,512]x[512,512]
    tgemm_kernel<0><<<dim3(512/128, TOT/128), 256, TGEMM_SMEM>>>(po, proj_w, proj_b, pproj, nullptr, TOT, 512, 512);
    // 5. window reverse + unshift + residual
    scatter_add_kernel<<<TOT, 128>>>(x, pproj, out);
    // 6. LN2
    ln_kernel<false><<<TOT, 128>>>(out, ln2_s, ln2_b, ph);
    // 7. FC1 + GELU [50176,512]x[512,2048]
    tgemm_kernel<1><<<dim3(HID/128, TOT/128), 256, TGEMM_SMEM>>>(ph, fc1_w, fc1_b, pact, nullptr, TOT, HID, 512);
    // 8. FC2 + residual [50176,2048]x[2048,512]
    tgemm_kernel<2><<<dim3(512/128, TOT/128), 256, TGEMM_SMEM>>>(pact, fc2_w, fc2_b, out, out, TOT, 512, HID);
}

// round 4
// speedup vs baseline: 2.7140x; 1.0888x over previous
#include <cuda_runtime.h>
#include <math.h>
#include <stdint.h>

// ---------------- problem constants ----------------
#define HH 56
#define WW_ 56
#define CC 512
#define NHEAD 16
#define WSZ 7
#define SSH 3
#define HID 2048
#define HD 32
#define NTOK 49           // tokens per window
#define NWH 8
#define NWW 8
#define NWIN 64
#define BB 16
#define TOT (BB*HH*WW_)   // 50176 tokens
#define LN_EPS 1e-5f
#define ATT_SCALE 0.17677669529663687f  // 32^-0.5

// ---------------- scratch (device globals, no allocs) ----------------
__device__ float g_h   [TOT * CC];        // LN1+windowed  (reused as h2)
__device__ float g_qkv [TOT * 3 * CC];    // qkv
__device__ float g_o   [TOT * CC];        // attention out (window layout)
__device__ float g_proj[TOT * CC];        // proj out (window layout)
__device__ float g_act [TOT * HID];       // fc1 activations

// ---------------- LayerNorm (optionally fused shift+window gather) ----------------
template<bool GATHER>
__global__ void ln_kernel(const float* __restrict__ src,
                          const float* __restrict__ scale,
                          const float* __restrict__ bias,
                          float* __restrict__ dst)
{
    int t = blockIdx.x;
    const float* sp;
    if (GATHER) {
        int b   = t / (NWIN * NTOK);
        int rem = t % (NWIN * NTOK);
        int win = rem / NTOK, pos = rem % NTOK;
        int wh = win / NWW, ww = win % NWW;
        int p = pos / WSZ, q = pos % WSZ;
        int row = (wh * WSZ + p + SSH) % HH;     // roll(-3)
        int col = (ww * WSZ + q + SSH) % WW_;
        sp = src + ((size_t)(b * HH + row) * WW_ + col) * CC;
    } else {
        sp = src + (size_t)t * CC;
    }
    float* dp = dst + (size_t)t * CC;

    int tid = threadIdx.x;                 // 128 threads, 4 floats each
    float4 v = *(const float4*)(sp + tid * 4);
    float s  = v.x + v.y + v.z + v.w;
    float s2 = v.x*v.x + v.y*v.y + v.z*v.z + v.w*v.w;

    __shared__ float red[8];
    #pragma unroll
    for (int off = 16; off > 0; off >>= 1) {
        s  += __shfl_down_sync(0xffffffffu, s,  off);
        s2 += __shfl_down_sync(0xffffffffu, s2, off);
    }
    int wid = tid >> 5, lane = tid & 31;
    if (lane == 0) { red[wid] = s; red[4 + wid] = s2; }
    __syncthreads();
    if (tid == 0) {
        float S  = red[0] + red[1] + red[2] + red[3];
        float S2 = red[4] + red[5] + red[6] + red[7];
        float mu  = S * (1.0f / CC);
        float var = S2 * (1.0f / CC) - mu * mu;
        red[0] = mu;
        red[1] = rsqrtf(var + LN_EPS);
    }
    __syncthreads();
    float mu = red[0], rs = red[1];
    float4 sc = *(const float4*)(scale + tid * 4);
    float4 bi = *(const float4*)(bias  + tid * 4);
    float4 o;
    o.x = (v.x - mu) * rs * sc.x + bi.x;
    o.y = (v.y - mu) * rs * sc.y + bi.y;
    o.z = (v.z - mu) * rs * sc.z + bi.z;
    o.w = (v.w - mu) * rs * sc.w + bi.w;
    *(float4*)(dp + tid * 4) = o;
}

// ---------------- TF32 tensor-core GEMM, 128x256 block, 64x64 warp tile ----------------
__device__ __forceinline__ float gelu_exact(float x) {
    return 0.5f * x * (1.0f + erff(x * 0.70710678118654752f));
}
__device__ __forceinline__ uint32_t f2tf32(float x) {
    uint32_t r;
    asm("cvt.rna.tf32.f32 %0, %1;" : "=r"(r) : "f"(x));
    return r;
}
__device__ __forceinline__ void cp_async16(uint32_t dst, const void* src) {
    asm volatile("cp.async.cg.shared.global [%0], [%1], 16;" :: "r"(dst), "l"(src));
}

#define SST 136   // A smem row stride (floats)
#define BST 264   // B smem row stride (floats)
#define KST 32    // k per stage
#define TG2_SMEM (2*KST*SST*4 + 2*KST*BST*4)   // 102400 bytes

template<int EPI>
__global__ __launch_bounds__(256, 1)
void tgemm_kernel(const float* __restrict__ A, const float* __restrict__ B,
                  const float* __restrict__ bias, float* __restrict__ Cout,
                  const float* __restrict__ res, int M, int N, int K)
{
    extern __shared__ float sh[];
    float* As = sh;                       // [2][KST][SST]
    float* Bs = sh + 2 * KST * SST;       // [2][KST][BST]

    const int bx = blockIdx.x;            // N tile (256)
    const int by = blockIdx.y;            // M tile (128)
    const int tid = threadIdx.x;
    const int wid = tid >> 5, lane = tid & 31;
    const int wm = wid & 1;               // 2 warps in M (64 rows each)
    const int wn = wid >> 1;              // 4 warps in N (64 cols each)
    const int lr = lane >> 2;             // 0..7
    const int lc = lane & 3;              // 0..3

    float acc[4][8][4];
    #pragma unroll
    for (int i = 0; i < 4; i++)
        #pragma unroll
        for (int j = 0; j < 8; j++) {
            acc[i][j][0] = 0.f; acc[i][j][1] = 0.f;
            acc[i][j][2] = 0.f; acc[i][j][3] = 0.f;
        }

    // A staging: thread -> (row, k-half)
    const int a_row = tid >> 1;
    const int a_k0  = (tid & 1) * 16;
    const float* Ag = A + (size_t)(by * 128 + a_row) * K + a_k0;

    // B staging via cp.async: thread -> row (0..31), 8 x 16B chunks
    const int b_row = tid >> 3;
    const int b_c0  = (tid & 7) * 4;      // float offset of first chunk
    const float* Bg = B + (size_t)b_row * N + bx * 256 + b_c0;

    const int NS = K / KST;

    float4 ra[4];

    // ---- prologue: stage 0 ----
    #pragma unroll
    for (int j = 0; j < 4; j++) ra[j] = *(const float4*)(Ag + j * 4);
    {
        uint32_t bdst = (uint32_t)__cvta_generic_to_shared(Bs + b_row * BST + b_c0);
        #pragma unroll
        for (int c = 0; c < 8; c++)
            cp_async16(bdst + c * 32 * 4, Bg + c * 32);
        asm volatile("cp.async.commit_group;");
    }
    #pragma unroll
    for (int j = 0; j < 4; j++) {
        As[(a_k0 + j*4 + 0) * SST + a_row] = __uint_as_float(f2tf32(ra[j].x));
        As[(a_k0 + j*4 + 1) * SST + a_row] = __uint_as_float(f2tf32(ra[j].y));
        As[(a_k0 + j*4 + 2) * SST + a_row] = __uint_as_float(f2tf32(ra[j].z));
        As[(a_k0 + j*4 + 3) * SST + a_row] = __uint_as_float(f2tf32(ra[j].w));
    }
    asm volatile("cp.async.wait_group 0;");
    __syncthreads();

    for (int s = 0; s < NS; s++) {
        // prefetch next stage
        if (s + 1 < NS) {
            const float* Agn = Ag + (s + 1) * KST;
            #pragma unroll
            for (int j = 0; j < 4; j++) ra[j] = *(const float4*)(Agn + j * 4);
            float* Bbuf = Bs + ((s + 1) & 1) * KST * BST;
            uint32_t bdst = (uint32_t)__cvta_generic_to_shared(Bbuf + b_row * BST + b_c0);
            const float* Bgn = Bg + (size_t)(s + 1) * KST * N;
            #pragma unroll
            for (int c = 0; c < 8; c++)
                cp_async16(bdst + c * 32 * 4, Bgn + c * 32);
            asm volatile("cp.async.commit_group;");
        }

        const float* Ab = As + (s & 1) * KST * SST;
        const float* Bb = Bs + (s & 1) * KST * BST;

        #pragma unroll
        for (int kk = 0; kk < KST; kk += 8) {
            uint32_t af[4][4], bf[8][2];
            #pragma unroll
            for (int mi = 0; mi < 4; mi++) {
                int m = wm * 64 + mi * 16 + lr;
                af[mi][0] = __float_as_uint(Ab[(kk + lc    ) * SST + m]);
                af[mi][1] = __float_as_uint(Ab[(kk + lc    ) * SST + m + 8]);
                af[mi][2] = __float_as_uint(Ab[(kk + lc + 4) * SST + m]);
                af[mi][3] = __float_as_uint(Ab[(kk + lc + 4) * SST + m + 8]);
            }
            #pragma unroll
            for (int ni = 0; ni < 8; ni++) {
                int n = wn * 64 + ni * 8 + lr;
                bf[ni][0] = __float_as_uint(Bb[(kk + lc    ) * BST + n]);
                bf[ni][1] = __float_as_uint(Bb[(kk + lc + 4) * BST + n]);
            }
            #pragma unroll
            for (int mi = 0; mi < 4; mi++)
                #pragma unroll
                for (int ni = 0; ni < 8; ni++) {
                    asm volatile(
                        "mma.sync.aligned.m16n8k8.row.col.f32.tf32.tf32.f32 "
                        "{%0,%1,%2,%3}, {%4,%5,%6,%7}, {%8,%9}, {%0,%1,%2,%3};"
                        : "+f"(acc[mi][ni][0]), "+f"(acc[mi][ni][1]),
                          "+f"(acc[mi][ni][2]), "+f"(acc[mi][ni][3])
                        : "r"(af[mi][0]), "r"(af[mi][1]), "r"(af[mi][2]), "r"(af[mi][3]),
                          "r"(bf[ni][0]), "r"(bf[ni][1]));
                }
        }

        if (s + 1 < NS) {
            float* Ad = As + ((s + 1) & 1) * KST * SST;
            #pragma unroll
            for (int j = 0; j < 4; j++) {
                Ad[(a_k0 + j*4 + 0) * SST + a_row] = __uint_as_float(f2tf32(ra[j].x));
                Ad[(a_k0 + j*4 + 1) * SST + a_row] = __uint_as_float(f2tf32(ra[j].y));
                Ad[(a_k0 + j*4 + 2) * SST + a_row] = __uint_as_float(f2tf32(ra[j].z));
                Ad[(a_k0 + j*4 + 3) * SST + a_row] = __uint_as_float(f2tf32(ra[j].w));
            }
            asm volatile("cp.async.wait_group 0;");
        }
        __syncthreads();
    }

    // ---------------- epilogue ----------------
    const int m_base = by * 128 + wm * 64;
    const int n_base = bx * 256 + wn * 64;

    float2 bv[8];
    #pragma unroll
    for (int ni = 0; ni < 8; ni++)
        bv[ni] = *(const float2*)(bias + n_base + ni * 8 + 2 * lc);

    #pragma unroll
    for (int mi = 0; mi < 4; mi++) {
        int r0 = m_base + mi * 16 + lr;
        int r1 = r0 + 8;
        #pragma unroll
        for (int ni = 0; ni < 8; ni++) {
            int col = n_base + ni * 8 + 2 * lc;
            size_t off0 = (size_t)r0 * N + col;
            size_t off1 = (size_t)r1 * N + col;
            float2 v0, v1;
            v0.x = acc[mi][ni][0] + bv[ni].x;
            v0.y = acc[mi][ni][1] + bv[ni].y;
            v1.x = acc[mi][ni][2] + bv[ni].x;
            v1.y = acc[mi][ni][3] + bv[ni].y;
            if (EPI == 1) {
                v0.x = gelu_exact(v0.x); v0.y = gelu_exact(v0.y);
                v1.x = gelu_exact(v1.x); v1.y = gelu_exact(v1.y);
            }
            if (EPI == 2) {
                float2 q0 = *(const float2*)(res + off0);
                float2 q1 = *(const float2*)(res + off1);
                v0.x += q0.x; v0.y += q0.y;
                v1.x += q1.x; v1.y += q1.y;
            }
            *(float2*)(Cout + off0) = v0;
            *(float2*)(Cout + off1) = v1;
        }
    }
}

// ---------------- windowed attention: one block per (window, head) ----------------
__global__ void attn_kernel(const float* __restrict__ qkv,
                            const float* __restrict__ rpb_table,
                            float* __restrict__ o)
{
    int head = blockIdx.x;
    int win  = blockIdx.y;             // b*NWIN + w
    int wloc = win % NWIN;
    int wh = wloc / NWW, ww = wloc % NWW;

    __shared__ float Qs[NTOK][33];
    __shared__ float Ks[NTOK][33];
    __shared__ float Vs[NTOK][33];
    __shared__ float Ss[NTOK][NTOK];
    __shared__ float rpbs[169];
    __shared__ int   regn[NTOK];

    int tid = threadIdx.x;             // 128

    const float* base = qkv + (size_t)win * NTOK * (3 * CC) + head * HD;
    for (int i = tid; i < NTOK * 8; i += 128) {
        int n = i >> 3, d4 = (i & 7) * 4;
        const float* rp = base + (size_t)n * (3 * CC);
        float4 q4 = *(const float4*)(rp + d4);
        float4 k4 = *(const float4*)(rp + CC + d4);
        float4 v4 = *(const float4*)(rp + 2 * CC + d4);
        Qs[n][d4] = q4.x; Qs[n][d4+1] = q4.y; Qs[n][d4+2] = q4.z; Qs[n][d4+3] = q4.w;
        Ks[n][d4] = k4.x; Ks[n][d4+1] = k4.y; Ks[n][d4+2] = k4.z; Ks[n][d4+3] = k4.w;
        Vs[n][d4] = v4.x; Vs[n][d4+1] = v4.y; Vs[n][d4+2] = v4.z; Vs[n][d4+3] = v4.w;
    }
    for (int i = tid; i < 169; i += 128) rpbs[i] = rpb_table[i * NHEAD + head];
    if (tid < NTOK) {
        int p = tid / WSZ, q = tid % WSZ;
        int r = wh * WSZ + p, c = ww * WSZ + q;       // shifted-frame coords
        int rr = (r < 49) ? 0 : ((r < 53) ? 1 : 2);
        int rc = (c < 49) ? 0 : ((c < 53) ? 1 : 2);
        regn[tid] = rr * 3 + rc;
    }
    __syncthreads();

    // scores + rpb + mask
    for (int i = tid; i < NTOK * NTOK; i += 128) {
        int n = i / NTOK, m = i % NTOK;
        float acc = 0.0f;
        #pragma unroll
        for (int d = 0; d < HD; d++) acc += Qs[n][d] * Ks[m][d];
        int in_ = n / WSZ, jn = n % WSZ;
        int im  = m / WSZ, jm = m % WSZ;
        int ridx = (jn - jm + 6) * 13 + (in_ - im + 6);
        float val = acc * ATT_SCALE + rpbs[ridx];
        if (regn[n] != regn[m]) val -= 100.0f;
        Ss[n][m] = val;
    }
    __syncthreads();

    // row softmax (thread r owns row r)
    if (tid < NTOK) {
        float mx = -1e30f;
        #pragma unroll 7
        for (int m = 0; m < NTOK; m++) mx = fmaxf(mx, Ss[tid][m]);
        float sum = 0.0f;
        #pragma unroll 7
        for (int m = 0; m < NTOK; m++) {
            float e = expf(Ss[tid][m] - mx);
            Ss[tid][m] = e;
            sum += e;
        }
        float inv = 1.0f / sum;
        #pragma unroll 7
        for (int m = 0; m < NTOK; m++) Ss[tid][m] *= inv;
    }
    __syncthreads();

    // O = P @ V
    float* obase = o + (size_t)win * NTOK * CC + head * HD;
    for (int i = tid; i < NTOK * HD; i += 128) {
        int n = i >> 5, d = i & 31;
        float acc = 0.0f;
        #pragma unroll 7
        for (int m = 0; m < NTOK; m++) acc += Ss[n][m] * Vs[m][d];
        obase[(size_t)n * CC + d] = acc;
    }
}

// ---------------- window reverse + unshift + residual ----------------
__global__ void scatter_add_kernel(const float* __restrict__ x,
                                   const float* __restrict__ p,
                                   float* __restrict__ y)
{
    int t = blockIdx.x;
    int b = t / (HH * WW_);
    int rem = t % (HH * WW_);
    int r = rem / WW_, c = rem % WW_;
    int R  = (r - SSH + HH) % HH;       // reverse roll(+3)
    int Cc = (c - SSH + WW_) % WW_;
    int win = (R / WSZ) * NWW + (Cc / WSZ);
    int pos = (R % WSZ) * WSZ + (Cc % WSZ);
    const float* sp = p + ((size_t)(b * NWIN + win) * NTOK + pos) * CC;
    const float* xp = x + (size_t)t * CC;
    float* yp = y + (size_t)t * CC;
    int tid = threadIdx.x;
    float4 a  = *(const float4*)(xp + tid * 4);
    float4 pr = *(const float4*)(sp + tid * 4);
    float4 o;
    o.x = a.x + pr.x; o.y = a.y + pr.y; o.z = a.z + pr.z; o.w = a.w + pr.w;
    *(float4*)(yp + tid * 4) = o;
}

// ---------------- host launcher ----------------
extern "C" void kernel_launch(void* const* d_in, const int* in_sizes, int n_in,
                              void* d_out, int out_size)
{
    const float* x      = (const float*)d_in[0];
    const float* ln1_s  = (const float*)d_in[1];
    const float* ln1_b  = (const float*)d_in[2];
    const float* qkv_w  = (const float*)d_in[3];
    const float* qkv_b  = (const float*)d_in[4];
    const float* rpb    = (const float*)d_in[5];
    const float* proj_w = (const float*)d_in[6];
    const float* proj_b = (const float*)d_in[7];
    const float* ln2_s  = (const float*)d_in[8];
    const float* ln2_b  = (const float*)d_in[9];
    const float* fc1_w  = (const float*)d_in[10];
    const float* fc1_b  = (const float*)d_in[11];
    const float* fc2_w  = (const float*)d_in[12];
    const float* fc2_b  = (const float*)d_in[13];
    float* out = (float*)d_out;

    float *ph, *pqkv, *po, *pproj, *pact;
    cudaGetSymbolAddress((void**)&ph,    g_h);
    cudaGetSymbolAddress((void**)&pqkv,  g_qkv);
    cudaGetSymbolAddress((void**)&po,    g_o);
    cudaGetSymbolAddress((void**)&pproj, g_proj);
    cudaGetSymbolAddress((void**)&pact,  g_act);

    static int smem_set = 0;
    if (!smem_set) {
        cudaFuncSetAttribute(tgemm_kernel<0>, cudaFuncAttributeMaxDynamicSharedMemorySize, TG2_SMEM);
        cudaFuncSetAttribute(tgemm_kernel<1>, cudaFuncAttributeMaxDynamicSharedMemorySize, TG2_SMEM);
        cudaFuncSetAttribute(tgemm_kernel<2>, cudaFuncAttributeMaxDynamicSharedMemorySize, TG2_SMEM);
        smem_set = 1;
    }

    // 1. LN1 + shift + window partition
    ln_kernel<true><<<TOT, 128>>>(x, ln1_s, ln1_b, ph);
    // 2. QKV GEMM [50176,512]x[512,1536]
    tgemm_kernel<0><<<dim3(1536/256, TOT/128), 256, TG2_SMEM>>>(ph, qkv_w, qkv_b, pqkv, nullptr, TOT, 1536, 512);
    // 3. windowed attention
    attn_kernel<<<dim3(NHEAD, BB * NWIN), 128>>>(pqkv, rpb, po);
    // 4. proj GEMM [50176,512]x[512,512]
    tgemm_kernel<0><<<dim3(512/256, TOT/128), 256, TG2_SMEM>>>(po, proj_w, proj_b, pproj, nullptr, TOT, 512, 512);
    // 5. window reverse + unshift + residual
    scatter_add_kernel<<<TOT, 128>>>(x, pproj, out);
    // 6. LN2
    ln_kernel<false><<<TOT, 128>>>(out, ln2_s, ln2_b, ph);
    // 7. FC1 + GELU [50176,512]x[512,2048]
    tgemm_kernel<1><<<dim3(HID/256, TOT/128), 256, TG2_SMEM>>>(ph, fc1_w, fc1_b, pact, nullptr, TOT, HID, 512);
    // 8. FC2 + residual [50176,2048]x[2048,512]
    tgemm_kernel<2><<<dim3(512/256, TOT/128), 256, TG2_SMEM>>>(pact, fc2_w, fc2_b, out, out, TOT, 512, HID);
}

// round 5
// speedup vs baseline: 2.7627x; 1.0179x over previous
#include <cuda_runtime.h>
#include <math.h>
#include <stdint.h>

// ---------------- problem constants ----------------
#define HH 56
#define WW_ 56
#define CC 512
#define NHEAD 16
#define WSZ 7
#define SSH 3
#define HID 2048
#define HD 32
#define NTOK 49           // tokens per window
#define NWH 8
#define NWW 8
#define NWIN 64
#define BB 16
#define TOT (BB*HH*WW_)   // 50176 tokens
#define LN_EPS 1e-5f
#define ATT_SCALE 0.17677669529663687f  // 32^-0.5

// ---------------- scratch (device globals, no allocs) ----------------
__device__ float g_h   [TOT * CC];        // LN1+windowed  (reused as h2)
__device__ float g_qkv [TOT * 3 * CC];    // qkv
__device__ float g_o   [TOT * CC];        // attention out (window layout)
__device__ float g_act [TOT * HID];       // fc1 activations

// ---------------- LayerNorm (optionally fused shift+window gather) ----------------
template<bool GATHER>
__global__ void ln_kernel(const float* __restrict__ src,
                          const float* __restrict__ scale,
                          const float* __restrict__ bias,
                          float* __restrict__ dst)
{
    int t = blockIdx.x;
    const float* sp;
    if (GATHER) {
        int b   = t / (NWIN * NTOK);
        int rem = t % (NWIN * NTOK);
        int win = rem / NTOK, pos = rem % NTOK;
        int wh = win / NWW, ww = win % NWW;
        int p = pos / WSZ, q = pos % WSZ;
        int row = (wh * WSZ + p + SSH) % HH;     // roll(-3)
        int col = (ww * WSZ + q + SSH) % WW_;
        sp = src + ((size_t)(b * HH + row) * WW_ + col) * CC;
    } else {
        sp = src + (size_t)t * CC;
    }
    float* dp = dst + (size_t)t * CC;

    int tid = threadIdx.x;                 // 128 threads, 4 floats each
    float4 v = *(const float4*)(sp + tid * 4);
    float s  = v.x + v.y + v.z + v.w;
    float s2 = v.x*v.x + v.y*v.y + v.z*v.z + v.w*v.w;

    __shared__ float red[8];
    #pragma unroll
    for (int off = 16; off > 0; off >>= 1) {
        s  += __shfl_down_sync(0xffffffffu, s,  off);
        s2 += __shfl_down_sync(0xffffffffu, s2, off);
    }
    int wid = tid >> 5, lane = tid & 31;
    if (lane == 0) { red[wid] = s; red[4 + wid] = s2; }
    __syncthreads();
    if (tid == 0) {
        float S  = red[0] + red[1] + red[2] + red[3];
        float S2 = red[4] + red[5] + red[6] + red[7];
        float mu  = S * (1.0f / CC);
        float var = S2 * (1.0f / CC) - mu * mu;
        red[0] = mu;
        red[1] = rsqrtf(var + LN_EPS);
    }
    __syncthreads();
    float mu = red[0], rs = red[1];
    float4 sc = *(const float4*)(scale + tid * 4);
    float4 bi = *(const float4*)(bias  + tid * 4);
    float4 o;
    o.x = (v.x - mu) * rs * sc.x + bi.x;
    o.y = (v.y - mu) * rs * sc.y + bi.y;
    o.z = (v.z - mu) * rs * sc.z + bi.z;
    o.w = (v.w - mu) * rs * sc.w + bi.w;
    *(float4*)(dp + tid * 4) = o;
}

// ---------------- TF32 tensor-core GEMM, 128x128 block, 4 warps, 64x64 warp tile ----------------
__device__ __forceinline__ float gelu_exact(float x) {
    return 0.5f * x * (1.0f + erff(x * 0.70710678118654752f));
}
__device__ __forceinline__ uint32_t f2tf32(float x) {
    uint32_t r;
    asm("cvt.rna.tf32.f32 %0, %1;" : "=r"(r) : "f"(x));
    return r;
}
__device__ __forceinline__ void cp_async16(uint32_t dst, const void* src) {
    asm volatile("cp.async.cg.shared.global [%0], [%1], 16;" :: "r"(dst), "l"(src));
}

#define SST 136   // smem row stride (floats): (8*lc + lr) covers all 32 banks
#define KST 32    // k per stage
#define TG_SMEM (2*KST*SST*4*2)   // 69632 bytes (A + B, double buffered)

// EPI: 0=bias, 1=bias+GELU, 2=bias+residual, 3=bias+window-reverse-scatter+residual
template<int EPI>
__global__ __launch_bounds__(128, 2)
void tgemm_kernel(const float* __restrict__ A, const float* __restrict__ B,
                  const float* __restrict__ bias, float* __restrict__ Cout,
                  const float* __restrict__ res, int M, int N, int K)
{
    extern __shared__ float sh[];
    float* As = sh;                       // [2][KST][SST]
    float* Bs = sh + 2 * KST * SST;       // [2][KST][SST]

    const int bx = blockIdx.x;            // N tile (128)
    const int by = blockIdx.y;            // M tile (128)
    const int tid = threadIdx.x;          // 128
    const int wid = tid >> 5, lane = tid & 31;
    const int wm = wid & 1;               // 2 warps in M (64 rows each)
    const int wn = wid >> 1;              // 2 warps in N (64 cols each)
    const int lr = lane >> 2;             // 0..7
    const int lc = lane & 3;              // 0..3

    float acc[4][8][4];
    #pragma unroll
    for (int i = 0; i < 4; i++)
        #pragma unroll
        for (int j = 0; j < 8; j++) {
            acc[i][j][0] = 0.f; acc[i][j][1] = 0.f;
            acc[i][j][2] = 0.f; acc[i][j][3] = 0.f;
        }

    // A staging: thread -> rows (tid>>1, 64+tid>>1), k-half (tid&1)*16
    const int a_row = tid >> 1;
    const int a_k0  = (tid & 1) * 16;
    const float* Ag0 = A + (size_t)(by * 128 + a_row) * K + a_k0;
    const float* Ag1 = Ag0 + (size_t)64 * K;

    // B staging via cp.async: thread -> row tid>>2 (0..31), 8 x 16B chunks
    const int b_row = tid >> 2;
    const int b_c0  = (tid & 3) * 4;
    const float* Bg = B + (size_t)b_row * N + bx * 128 + b_c0;

    const int NS = K / KST;

    float4 ra[8];

    // ---- prologue: stage 0 ----
    #pragma unroll
    for (int j = 0; j < 4; j++) {
        ra[j]     = *(const float4*)(Ag0 + j * 4);
        ra[4 + j] = *(const float4*)(Ag1 + j * 4);
    }
    {
        uint32_t bdst = (uint32_t)__cvta_generic_to_shared(Bs + b_row * SST + b_c0);
        #pragma unroll
        for (int c = 0; c < 8; c++)
            cp_async16(bdst + c * 16 * 4, Bg + c * 16);
        asm volatile("cp.async.commit_group;");
    }
    #pragma unroll
    for (int j = 0; j < 4; j++) {
        const float* f0 = (const float*)&ra[j];
        const float* f1 = (const float*)&ra[4 + j];
        #pragma unroll
        for (int e = 0; e < 4; e++) {
            As[(a_k0 + j*4 + e) * SST + a_row]      = __uint_as_float(f2tf32(f0[e]));
            As[(a_k0 + j*4 + e) * SST + a_row + 64] = __uint_as_float(f2tf32(f1[e]));
        }
    }
    asm volatile("cp.async.wait_group 0;");
    __syncthreads();

    for (int s = 0; s < NS; s++) {
        if (s + 1 < NS) {
            int k0 = (s + 1) * KST;
            #pragma unroll
            for (int j = 0; j < 4; j++) {
                ra[j]     = *(const float4*)(Ag0 + k0 + j * 4);
                ra[4 + j] = *(const float4*)(Ag1 + k0 + j * 4);
            }
            float* Bbuf = Bs + ((s + 1) & 1) * KST * SST;
            uint32_t bdst = (uint32_t)__cvta_generic_to_shared(Bbuf + b_row * SST + b_c0);
            const float* Bgn = Bg + (size_t)k0 * N;
            #pragma unroll
            for (int c = 0; c < 8; c++)
                cp_async16(bdst + c * 16 * 4, Bgn + c * 16);
            asm volatile("cp.async.commit_group;");
        }

        const float* Ab = As + (s & 1) * KST * SST;
        const float* Bb = Bs + (s & 1) * KST * SST;

        #pragma unroll
        for (int kk = 0; kk < KST; kk += 8) {
            uint32_t af[4][4], bf[8][2];
            #pragma unroll
            for (int mi = 0; mi < 4; mi++) {
                int m = wm * 64 + mi * 16 + lr;
                af[mi][0] = __float_as_uint(Ab[(kk + lc    ) * SST + m]);
                af[mi][1] = __float_as_uint(Ab[(kk + lc    ) * SST + m + 8]);
                af[mi][2] = __float_as_uint(Ab[(kk + lc + 4) * SST + m]);
                af[mi][3] = __float_as_uint(Ab[(kk + lc + 4) * SST + m + 8]);
            }
            #pragma unroll
            for (int ni = 0; ni < 8; ni++) {
                int n = wn * 64 + ni * 8 + lr;
                bf[ni][0] = __float_as_uint(Bb[(kk + lc    ) * SST + n]);
                bf[ni][1] = __float_as_uint(Bb[(kk + lc + 4) * SST + n]);
            }
            #pragma unroll
            for (int mi = 0; mi < 4; mi++)
                #pragma unroll
                for (int ni = 0; ni < 8; ni++) {
                    asm volatile(
                        "mma.sync.aligned.m16n8k8.row.col.f32.tf32.tf32.f32 "
                        "{%0,%1,%2,%3}, {%4,%5,%6,%7}, {%8,%9}, {%0,%1,%2,%3};"
                        : "+f"(acc[mi][ni][0]), "+f"(acc[mi][ni][1]),
                          "+f"(acc[mi][ni][2]), "+f"(acc[mi][ni][3])
                        : "r"(af[mi][0]), "r"(af[mi][1]), "r"(af[mi][2]), "r"(af[mi][3]),
                          "r"(bf[ni][0]), "r"(bf[ni][1]));
                }
        }

        if (s + 1 < NS) {
            float* Ad = As + ((s + 1) & 1) * KST * SST;
            #pragma unroll
            for (int j = 0; j < 4; j++) {
                const float* f0 = (const float*)&ra[j];
                const float* f1 = (const float*)&ra[4 + j];
                #pragma unroll
                for (int e = 0; e < 4; e++) {
                    Ad[(a_k0 + j*4 + e) * SST + a_row]      = __uint_as_float(f2tf32(f0[e]));
                    Ad[(a_k0 + j*4 + e) * SST + a_row + 64] = __uint_as_float(f2tf32(f1[e]));
                }
            }
            asm volatile("cp.async.wait_group 0;");
        }
        __syncthreads();
    }

    // ---------------- epilogue ----------------
    const int m_base = by * 128 + wm * 64;
    const int n_base = bx * 128 + wn * 64;

    float2 bv[8];
    #pragma unroll
    for (int ni = 0; ni < 8; ni++)
        bv[ni] = *(const float2*)(bias + n_base + ni * 8 + 2 * lc);

    #pragma unroll
    for (int mi = 0; mi < 4; mi++) {
        int r0 = m_base + mi * 16 + lr;
        int r1 = r0 + 8;
        size_t orow0 = (size_t)r0, orow1 = (size_t)r1;
        if (EPI == 3) {
            // window layout row -> spatial row (reverse shift + window reverse)
            int rows[2] = {r0, r1};
            size_t mapped[2];
            #pragma unroll
            for (int u = 0; u < 2; u++) {
                int t = rows[u];
                int b   = t / (NWIN * NTOK);
                int rem = t % (NWIN * NTOK);
                int win = rem / NTOK, pos = rem % NTOK;
                int wh = win >> 3, ww = win & 7;
                int p = pos / WSZ, q = pos % WSZ;
                int r = wh * WSZ + p + SSH; if (r >= HH) r -= HH;
                int c = ww * WSZ + q + SSH; if (c >= WW_) c -= WW_;
                mapped[u] = (size_t)(b * HH + r) * WW_ + c;
            }
            orow0 = mapped[0]; orow1 = mapped[1];
        }
        #pragma unroll
        for (int ni = 0; ni < 8; ni++) {
            int col = n_base + ni * 8 + 2 * lc;
            size_t off0 = orow0 * N + col;
            size_t off1 = orow1 * N + col;
            float2 v0, v1;
            v0.x = acc[mi][ni][0] + bv[ni].x;
            v0.y = acc[mi][ni][1] + bv[ni].y;
            v1.x = acc[mi][ni][2] + bv[ni].x;
            v1.y = acc[mi][ni][3] + bv[ni].y;
            if (EPI == 1) {
                v0.x = gelu_exact(v0.x); v0.y = gelu_exact(v0.y);
                v1.x = gelu_exact(v1.x); v1.y = gelu_exact(v1.y);
            }
            if (EPI == 2 || EPI == 3) {
                float2 q0 = *(const float2*)(res + off0);
                float2 q1 = *(const float2*)(res + off1);
                v0.x += q0.x; v0.y += q0.y;
                v1.x += q1.x; v1.y += q1.y;
            }
            *(float2*)(Cout + off0) = v0;
            *(float2*)(Cout + off1) = v1;
        }
    }
}

// ---------------- windowed attention: one block per (window, head) ----------------
__global__ void attn_kernel(const float* __restrict__ qkv,
                            const float* __restrict__ rpb_table,
                            float* __restrict__ o)
{
    int head = blockIdx.x;
    int win  = blockIdx.y;             // b*NWIN + w
    int wloc = win % NWIN;
    int wh = wloc / NWW, ww = wloc % NWW;

    __shared__ float Qs[NTOK][33];
    __shared__ float Ks[NTOK][33];
    __shared__ float Vs[NTOK][33];
    __shared__ float Ss[NTOK][NTOK];
    __shared__ float rpbs[169];
    __shared__ int   regn[NTOK];

    int tid = threadIdx.x;             // 128

    const float* base = qkv + (size_t)win * NTOK * (3 * CC) + head * HD;
    for (int i = tid; i < NTOK * 8; i += 128) {
        int n = i >> 3, d4 = (i & 7) * 4;
        const float* rp = base + (size_t)n * (3 * CC);
        float4 q4 = *(const float4*)(rp + d4);
        float4 k4 = *(const float4*)(rp + CC + d4);
        float4 v4 = *(const float4*)(rp + 2 * CC + d4);
        Qs[n][d4] = q4.x; Qs[n][d4+1] = q4.y; Qs[n][d4+2] = q4.z; Qs[n][d4+3] = q4.w;
        Ks[n][d4] = k4.x; Ks[n][d4+1] = k4.y; Ks[n][d4+2] = k4.z; Ks[n][d4+3] = k4.w;
        Vs[n][d4] = v4.x; Vs[n][d4+1] = v4.y; Vs[n][d4+2] = v4.z; Vs[n][d4+3] = v4.w;
    }
    for (int i = tid; i < 169; i += 128) rpbs[i] = rpb_table[i * NHEAD + head];
    if (tid < NTOK) {
        int p = tid / WSZ, q = tid % WSZ;
        int r = wh * WSZ + p, c = ww * WSZ + q;       // shifted-frame coords
        int rr = (r < 49) ? 0 : ((r < 53) ? 1 : 2);
        int rc = (c < 49) ? 0 : ((c < 53) ? 1 : 2);
        regn[tid] = rr * 3 + rc;
    }
    __syncthreads();

    // scores + rpb + mask
    for (int i = tid; i < NTOK * NTOK; i += 128) {
        int n = i / NTOK, m = i % NTOK;
        float acc = 0.0f;
        #pragma unroll
        for (int d = 0; d < HD; d++) acc += Qs[n][d] * Ks[m][d];
        int in_ = n / WSZ, jn = n % WSZ;
        int im  = m / WSZ, jm = m % WSZ;
        int ridx = (jn - jm + 6) * 13 + (in_ - im + 6);
        float val = acc * ATT_SCALE + rpbs[ridx];
        if (regn[n] != regn[m]) val -= 100.0f;
        Ss[n][m] = val;
    }
    __syncthreads();

    // row softmax (thread r owns row r)
    if (tid < NTOK) {
        float mx = -1e30f;
        #pragma unroll 7
        for (int m = 0; m < NTOK; m++) mx = fmaxf(mx, Ss[tid][m]);
        float sum = 0.0f;
        #pragma unroll 7
        for (int m = 0; m < NTOK; m++) {
            float e = expf(Ss[tid][m] - mx);
            Ss[tid][m] = e;
            sum += e;
        }
        float inv = 1.0f / sum;
        #pragma unroll 7
        for (int m = 0; m < NTOK; m++) Ss[tid][m] *= inv;
    }
    __syncthreads();

    // O = P @ V
    float* obase = o + (size_t)win * NTOK * CC + head * HD;
    for (int i = tid; i < NTOK * HD; i += 128) {
        int n = i >> 5, d = i & 31;
        float acc = 0.0f;
        #pragma unroll 7
        for (int m = 0; m < NTOK; m++) acc += Ss[n][m] * Vs[m][d];
        obase[(size_t)n * CC + d] = acc;
    }
}

// ---------------- host launcher ----------------
extern "C" void kernel_launch(void* const* d_in, const int* in_sizes, int n_in,
                              void* d_out, int out_size)
{
    const float* x      = (const float*)d_in[0];
    const float* ln1_s  = (const float*)d_in[1];
    const float* ln1_b  = (const float*)d_in[2];
    const float* qkv_w  = (const float*)d_in[3];
    const float* qkv_b  = (const float*)d_in[4];
    const float* rpb    = (const float*)d_in[5];
    const float* proj_w = (const float*)d_in[6];
    const float* proj_b = (const float*)d_in[7];
    const float* ln2_s  = (const float*)d_in[8];
    const float* ln2_b  = (const float*)d_in[9];
    const float* fc1_w  = (const float*)d_in[10];
    const float* fc1_b  = (const float*)d_in[11];
    const float* fc2_w  = (const float*)d_in[12];
    const float* fc2_b  = (const float*)d_in[13];
    float* out = (float*)d_out;

    float *ph, *pqkv, *po, *pact;
    cudaGetSymbolAddress((void**)&ph,   g_h);
    cudaGetSymbolAddress((void**)&pqkv, g_qkv);
    cudaGetSymbolAddress((void**)&po,   g_o);
    cudaGetSymbolAddress((void**)&pact, g_act);

    static int smem_set = 0;
    if (!smem_set) {
        cudaFuncSetAttribute(tgemm_kernel<0>, cudaFuncAttributeMaxDynamicSharedMemorySize, TG_SMEM);
        cudaFuncSetAttribute(tgemm_kernel<1>, cudaFuncAttributeMaxDynamicSharedMemorySize, TG_SMEM);
        cudaFuncSetAttribute(tgemm_kernel<2>, cudaFuncAttributeMaxDynamicSharedMemorySize, TG_SMEM);
        cudaFuncSetAttribute(tgemm_kernel<3>, cudaFuncAttributeMaxDynamicSharedMemorySize, TG_SMEM);
        smem_set = 1;
    }

    // 1. LN1 + shift + window partition
    ln_kernel<true><<<TOT, 128>>>(x, ln1_s, ln1_b, ph);
    // 2. QKV GEMM [50176,512]x[512,1536]
    tgemm_kernel<0><<<dim3(1536/128, TOT/128), 128, TG_SMEM>>>(ph, qkv_w, qkv_b, pqkv, nullptr, TOT, 1536, 512);
    // 3. windowed attention
    attn_kernel<<<dim3(NHEAD, BB * NWIN), 128>>>(pqkv, rpb, po);
    // 4. proj GEMM + fused window-reverse scatter + residual -> out
    tgemm_kernel<3><<<dim3(512/128, TOT/128), 128, TG_SMEM>>>(po, proj_w, proj_b, out, x, TOT, 512, 512);
    // 5. LN2
    ln_kernel<false><<<TOT, 128>>>(out, ln2_s, ln2_b, ph);
    // 6. FC1 + GELU [50176,512]x[512,2048]
    tgemm_kernel<1><<<dim3(HID/128, TOT/128), 128, TG_SMEM>>>(ph, fc1_w, fc1_b, pact, nullptr, TOT, HID, 512);
    // 7. FC2 + residual [50176,2048]x[2048,512]
    tgemm_kernel<2><<<dim3(512/128, TOT/128), 128, TG_SMEM>>>(pact, fc2_w, fc2_b, out, out, TOT, 512, HID);
}